// round 1
// baseline (speedup 1.0000x reference)
#include <cuda_runtime.h>
#include <math.h>

// ---------------------------------------------------------------------------
// DifferentiablePersistence via scaling-and-squaring matrix exponential.
// tr(exp(-L/sigma)) = tr(p(X)^8192), X = L/(sigma*8192), p(z)=1-z+z^2/2.
// 13 batched 768^3 fp32 GEMMs per threshold (incl. Frobenius trick for the
// last squaring). All scratch in __device__ globals (no allocation).
// ---------------------------------------------------------------------------

constexpr int N    = 768;
constexpr int NT   = 50;      // thresholds
constexpr int RES  = 100;
constexpr int NL   = 5;
constexpr int NNB  = N * N;   // 589824
constexpr int FB   = 36;      // frobenius partial blocks per threshold
constexpr int KT   = 96;      // 768 / 8 k-tiles
constexpr float INVSM = 1.0f / (0.1f * 8192.0f);  // 1/(sigma*m)

__device__ float        g_D[NNB];
__device__ float        g_bufA[NT * NNB];
__device__ float        g_bufB[NT * NNB];
__device__ double       g_partial[NT * FB];
__device__ unsigned int g_maxbits;

// ---------------------------------------------------------------------------
__global__ void initKernel() { g_maxbits = 0u; }

// dist matrix + global max (bitwise atomicMax valid for non-negative floats)
__global__ void distKernel(const float* __restrict__ P) {
    int i = blockIdx.x;
    int j = blockIdx.y * 256 + threadIdx.x;
    float px = P[3 * i], py = P[3 * i + 1], pz = P[3 * i + 2];
    float dx = px - P[3 * j];
    float dy = py - P[3 * j + 1];
    float dz = pz - P[3 * j + 2];
    float d2 = dx * dx + dy * dy + dz * dz;
    float d  = (d2 > 0.0f) ? sqrtf(d2) : 0.0f;
    g_D[i * N + j] = d;

    __shared__ float red[256];
    red[threadIdx.x] = d;
    __syncthreads();
    for (int s = 128; s > 0; s >>= 1) {
        if (threadIdx.x < s) red[threadIdx.x] = fmaxf(red[threadIdx.x], red[threadIdx.x + s]);
        __syncthreads();
    }
    if (threadIdx.x == 0) atomicMax(&g_maxbits, __float_as_uint(red[0]));
}

// Build X[t] = (deg*I - A)/ (sigma*m), A = sigmoid((thr - d)/sigma).
// One block per (row, threshold). deg accumulated in fp64.
__global__ void buildXKernel() {
    int i   = blockIdx.x;
    int t   = blockIdx.y;
    int tid = threadIdx.x;
    float maxd = __uint_as_float(g_maxbits);
    float thr  = ((float)t / 49.0f) * maxd;

    float a[3];
    double s = 0.0;
#pragma unroll
    for (int q = 0; q < 3; ++q) {
        int j = tid + q * 256;
        float d  = g_D[i * N + j];
        float aa = 1.0f / (1.0f + expf((d - thr) * 10.0f));  // sigmoid((thr-d)/0.1)
        a[q] = aa;
        s += (double)aa;
    }
    __shared__ double red[256];
    red[tid] = s;
    __syncthreads();
    for (int st = 128; st > 0; st >>= 1) {
        if (tid < st) red[tid] += red[tid + st];
        __syncthreads();
    }
    float deg = (float)red[0];

    float* X = g_bufA + t * NNB + i * N;
#pragma unroll
    for (int q = 0; q < 3; ++q) {
        int j = tid + q * 256;
        float l = (j == i) ? (deg - a[q]) : (-a[q]);
        X[j] = l * INVSM;
    }
}

// ---------------------------------------------------------------------------
// Batched 768x768 fp32 GEMM, 128x128x8 tile, 256 threads, 8x8 per thread,
// double-buffered smem.  mode 0: C = I - A + 0.5*A*A (builds B0 from X)
//                        mode 1: C = A*A
// ab = 0: src g_bufA -> dst g_bufB ; ab = 1: src g_bufB -> dst g_bufA
// ---------------------------------------------------------------------------
__global__ void __launch_bounds__(256, 2) gemmKernel(int mode, int ab) {
    const float* __restrict__ A = (ab ? g_bufB : g_bufA) + (size_t)blockIdx.z * NNB;
    float* __restrict__ C       = (ab ? g_bufA : g_bufB) + (size_t)blockIdx.z * NNB;

    __shared__ float As[2][8][128];
    __shared__ float Bs[2][8][128];

    int t  = threadIdx.x;
    int m0 = blockIdx.y * 128, n0 = blockIdx.x * 128;
    int ar = t >> 1, ac = (t & 1) * 4;   // A tile: 128 rows x 8 k
    int br = t >> 5, bc = (t & 31) * 4;  // B tile: 8 k x 128 cols
    int tx = t & 15, ty = t >> 4;

    float acc[8][8];
#pragma unroll
    for (int i = 0; i < 8; ++i)
#pragma unroll
        for (int j = 0; j < 8; ++j) acc[i][j] = 0.0f;

    float4 pa = *(const float4*)(A + (m0 + ar) * N + ac);
    float4 pb = *(const float4*)(A + br * N + n0 + bc);
    As[0][ac + 0][ar] = pa.x; As[0][ac + 1][ar] = pa.y;
    As[0][ac + 2][ar] = pa.z; As[0][ac + 3][ar] = pa.w;
    *(float4*)&Bs[0][br][bc] = pb;
    __syncthreads();

    int cur = 0;
    for (int kt = 0; kt < KT; ++kt) {
        bool more = (kt + 1 < KT);
        if (more) {
            pa = *(const float4*)(A + (m0 + ar) * N + (kt + 1) * 8 + ac);
            pb = *(const float4*)(A + ((kt + 1) * 8 + br) * N + n0 + bc);
        }
#pragma unroll
        for (int kk = 0; kk < 8; ++kk) {
            float4 a0 = *(const float4*)&As[cur][kk][ty * 8];
            float4 a1 = *(const float4*)&As[cur][kk][ty * 8 + 4];
            float4 b0 = *(const float4*)&Bs[cur][kk][tx * 8];
            float4 b1 = *(const float4*)&Bs[cur][kk][tx * 8 + 4];
            float av[8] = {a0.x, a0.y, a0.z, a0.w, a1.x, a1.y, a1.z, a1.w};
            float bv[8] = {b0.x, b0.y, b0.z, b0.w, b1.x, b1.y, b1.z, b1.w};
#pragma unroll
            for (int i = 0; i < 8; ++i)
#pragma unroll
                for (int j = 0; j < 8; ++j) acc[i][j] += av[i] * bv[j];
        }
        if (more) {
            int nxt = cur ^ 1;
            As[nxt][ac + 0][ar] = pa.x; As[nxt][ac + 1][ar] = pa.y;
            As[nxt][ac + 2][ar] = pa.z; As[nxt][ac + 3][ar] = pa.w;
            *(float4*)&Bs[nxt][br][bc] = pb;
            __syncthreads();
            cur = nxt;
        }
    }

    // epilogue
#pragma unroll
    for (int i = 0; i < 8; ++i) {
        int gi = m0 + ty * 8 + i;
        int cb = n0 + tx * 8;
        float o[8];
        if (mode == 0) {
            float4 x0 = *(const float4*)(A + gi * N + cb);
            float4 x1 = *(const float4*)(A + gi * N + cb + 4);
            float xv[8] = {x0.x, x0.y, x0.z, x0.w, x1.x, x1.y, x1.z, x1.w};
#pragma unroll
            for (int j = 0; j < 8; ++j)
                o[j] = 0.5f * acc[i][j] - xv[j] + ((gi == cb + j) ? 1.0f : 0.0f);
        } else {
#pragma unroll
            for (int j = 0; j < 8; ++j) o[j] = acc[i][j];
        }
        *(float4*)(C + gi * N + cb)     = make_float4(o[0], o[1], o[2], o[3]);
        *(float4*)(C + gi * N + cb + 4) = make_float4(o[4], o[5], o[6], o[7]);
    }
}

// Frobenius norm^2 partials: tr(B^(2^13)) = ||B^(2^12)||_F^2 (B symmetric)
__global__ void frobKernel() {
    int t = blockIdx.x, blk = blockIdx.y, tid = threadIdx.x;
    const float* B = g_bufB + (size_t)t * NNB + blk * 16384;
    double s = 0.0;
#pragma unroll
    for (int it = 0; it < 16; ++it) {
        float4 v = *(const float4*)(B + it * 1024 + tid * 4);
        s += (double)v.x * v.x + (double)v.y * v.y +
             (double)v.z * v.z + (double)v.w * v.w;
    }
    __shared__ double red[256];
    red[tid] = s;
    __syncthreads();
    for (int st = 128; st > 0; st >>= 1) {
        if (tid < st) red[tid] += red[tid + st];
        __syncthreads();
    }
    if (tid == 0) g_partial[t * FB + blk] = red[0];
}

// Betti curve -> interp -> landscapes. Single block, deterministic sums.
__global__ void finalKernel(float* __restrict__ out) {
    int tid = threadIdx.x;  // 128 threads
    __shared__ float sb[NT];
    __shared__ float sbi[RES];
    __shared__ float ssm[RES];
    __shared__ float red[128];

    if (tid < NT) {
        double s = 0.0;
        for (int j = 0; j < FB; ++j) s += g_partial[tid * FB + j];
        sb[tid] = (float)s;
    }
    __syncthreads();

    if (tid < RES) {
        float pos  = (float)tid * (49.0f / 99.0f);
        int   i0   = (int)floorf(pos);
        if (i0 > 48) i0 = 48;
        if (i0 < 0)  i0 = 0;
        float frac = pos - (float)i0;
        sbi[tid] = sb[i0] * (1.0f - frac) + sb[i0 + 1] * frac;
    }
    __syncthreads();

    red[tid] = (tid < RES) ? sbi[tid] : -1e30f;
    __syncthreads();
    for (int s = 64; s > 0; s >>= 1) {
        if (tid < s) red[tid] = fmaxf(red[tid], red[tid + s]);
        __syncthreads();
    }
    float bmax = red[0];
    __syncthreads();
    if (tid < RES) out[tid] = sbi[tid] / (bmax + 1e-8f);

    for (int k = 1; k < NL; ++k) {
        int ks = 2 * k + 1, pad = k;  // 3,5,7,9 all <= 25
        __syncthreads();
        if (tid < RES) {
            float s = 0.0f;
            for (int j = -pad; j <= pad; ++j) {
                int idx = tid + j;
                idx = idx < 0 ? 0 : (idx > RES - 1 ? RES - 1 : idx);
                s += sbi[idx];
            }
            ssm[tid] = s / (float)ks;
        }
        __syncthreads();
        float d = 0.0f;
        if (tid < RES)
            d = (tid < RES - 1) ? (ssm[tid + 1] - ssm[tid])
                                : (ssm[RES - 1] - ssm[RES - 2]);
        red[tid] = (tid < RES) ? fabsf(d) : 0.0f;
        __syncthreads();
        for (int s2 = 64; s2 > 0; s2 >>= 1) {
            if (tid < s2) red[tid] = fmaxf(red[tid], red[tid + s2]);
            __syncthreads();
        }
        float dmax = red[0];
        __syncthreads();
        if (tid < RES) out[k * RES + tid] = d / (dmax + 1e-8f);
    }
}

// ---------------------------------------------------------------------------
extern "C" void kernel_launch(void* const* d_in, const int* in_sizes, int n_in,
                              void* d_out, int out_size) {
    const float* pts = (const float*)d_in[0];
    float* out = (float*)d_out;
    (void)in_sizes; (void)n_in; (void)out_size;

    initKernel<<<1, 1>>>();
    distKernel<<<dim3(N, 3), 256>>>(pts);
    buildXKernel<<<dim3(N, NT), 256>>>();

    dim3 gg(6, 6, NT);
    gemmKernel<<<gg, 256>>>(0, 0);         // X (bufA) -> B0 = I - X + X^2/2 (bufB)
    int ab = 1;
    for (int s = 0; s < 12; ++s) {         // B -> B^2, 12 times (ends in bufB)
        gemmKernel<<<gg, 256>>>(1, ab);
        ab ^= 1;
    }
    frobKernel<<<dim3(NT, FB), 256>>>();   // betti[t] = ||B||_F^2 partials
    finalKernel<<<1, 128>>>(out);
}

// round 3
// speedup vs baseline: 3.2833x; 3.2833x over previous
#include <cuda_runtime.h>
#include <cuda_fp16.h>
#include <math.h>
#include <stdint.h>

// ---------------------------------------------------------------------------
// DifferentiablePersistence via scaling-and-squaring matrix exponential on
// legacy tensor cores (mma.sync, fp16-split emulation of fp32).
// tr(exp(-L/sigma)) = tr(p(X)^8192), X = L/(sigma*8192), p(z)=1-z+z^2/2.
// All matrices stored as 256*value in (hi,lo) fp16 pairs (keeps lo normal).
// C = Ah*Bh + Ah*Bl + Al*Bh on m16n8k16 HMMA, fp32 accumulate.
// Symmetric: only blocks bm<=bn computed; mirror written via smem transpose.
// ---------------------------------------------------------------------------

constexpr int N    = 768;
constexpr int NT   = 50;
constexpr int RES  = 100;
constexpr int NL   = 5;
constexpr int NNB  = N * N;
constexpr float INVSM = 1.0f / (0.1f * 8192.0f);
constexpr float SC    = 256.0f;          // storage scale
constexpr int   KS    = 32;              // K per stage
constexpr int   NSTG  = 24;              // 768/32
constexpr int   STRIDE = 40;             // smem halves per row (conflict-free)
constexpr int   BUFB  = 10240;           // bytes per operand buffer (128*40*2)
constexpr int   STAGE_B = 4 * BUFB;      // Ah,Al,Bh,Bl
constexpr int   SMEM_BYTES = 3 * STAGE_B;

__device__ float  g_D[NNB];
__device__ __half g_Ahi[(size_t)NT * NNB];
__device__ __half g_Alo[(size_t)NT * NNB];
__device__ __half g_Bhi[(size_t)NT * NNB];
__device__ __half g_Blo[(size_t)NT * NNB];
__device__ double g_betti[NT];
__device__ unsigned int g_maxbits;

__device__ __forceinline__ uint32_t smem_u32(const void* p) {
    uint32_t a;
    asm("{ .reg .u64 t; cvta.to.shared.u64 t, %1; cvt.u32.u64 %0, t; }"
        : "=r"(a) : "l"(p));
    return a;
}

#define LDSM4(r, addr) \
    asm volatile("ldmatrix.sync.aligned.m8n8.x4.shared.b16 {%0,%1,%2,%3}, [%4];" \
        : "=r"((r)[0]), "=r"((r)[1]), "=r"((r)[2]), "=r"((r)[3]) : "r"(addr))

#define MMA(c, a, b0v, b1v) \
    asm volatile("mma.sync.aligned.m16n8k16.row.col.f32.f16.f16.f32 " \
        "{%0,%1,%2,%3}, {%4,%5,%6,%7}, {%8,%9}, {%0,%1,%2,%3};" \
        : "+f"((c)[0]), "+f"((c)[1]), "+f"((c)[2]), "+f"((c)[3]) \
        : "r"((a)[0]), "r"((a)[1]), "r"((a)[2]), "r"((a)[3]), "r"(b0v), "r"(b1v))

// ------------------------------ small kernels ------------------------------
__global__ void initKernel() {
    if (threadIdx.x < NT) g_betti[threadIdx.x] = 0.0;
    if (threadIdx.x == 0) g_maxbits = 0u;
}

__global__ void distKernel(const float* __restrict__ P) {
    int i = blockIdx.x;
    int j = blockIdx.y * 256 + threadIdx.x;
    float px = P[3 * i], py = P[3 * i + 1], pz = P[3 * i + 2];
    float dx = px - P[3 * j];
    float dy = py - P[3 * j + 1];
    float dz = pz - P[3 * j + 2];
    float d2 = dx * dx + dy * dy + dz * dz;
    float d  = (d2 > 0.0f) ? sqrtf(d2) : 0.0f;
    g_D[i * N + j] = d;

    __shared__ float red[256];
    red[threadIdx.x] = d;
    __syncthreads();
    for (int s = 128; s > 0; s >>= 1) {
        if (threadIdx.x < s) red[threadIdx.x] = fmaxf(red[threadIdx.x], red[threadIdx.x + s]);
        __syncthreads();
    }
    if (threadIdx.x == 0) atomicMax(&g_maxbits, __float_as_uint(red[0]));
}

// Build 256*X = 256*(deg*I - A)/(sigma*m) in fp16 hi/lo -> g_Ahi/g_Alo
__global__ void buildXKernel() {
    int i   = blockIdx.x;
    int t   = blockIdx.y;
    int tid = threadIdx.x;
    float maxd = __uint_as_float(g_maxbits);
    float thr  = ((float)t / 49.0f) * maxd;

    float a[3];
    double s = 0.0;
#pragma unroll
    for (int q = 0; q < 3; ++q) {
        int j = tid + q * 256;
        float d  = g_D[i * N + j];
        float aa = 1.0f / (1.0f + expf((d - thr) * 10.0f));
        a[q] = aa;
        s += (double)aa;
    }
    __shared__ double red[256];
    red[tid] = s;
    __syncthreads();
    for (int st = 128; st > 0; st >>= 1) {
        if (tid < st) red[tid] += red[tid + st];
        __syncthreads();
    }
    float deg = (float)red[0];

    size_t base = (size_t)t * NNB + (size_t)i * N;
#pragma unroll
    for (int q = 0; q < 3; ++q) {
        int j = tid + q * 256;
        float l = (j == i) ? (deg - a[q]) : (-a[q]);
        float x  = l * INVSM * SC;
        __half hi = __float2half_rn(x);
        __half lo = __float2half_rn(x - __half2float(hi));
        g_Ahi[base + j] = hi;
        g_Alo[base + j] = lo;
    }
}

// --------------------------- GEMM stage loader -----------------------------
__device__ __forceinline__ void issue_stage(
    uint32_t stg, const __half* __restrict__ Shi, const __half* __restrict__ Slo,
    int m0, int n0, int k0, int tid)
{
#pragma unroll
    for (int i = 0; i < 8; ++i) {
        int c   = tid + i * 256;
        int buf = c >> 9;                 // 0:Ah 1:Al 2:Bh 3:Bl
        int row = (c >> 2) & 127;
        int sub = c & 3;
        const __half* sp = (buf & 1) ? Slo : Shi;
        int rb = (buf & 2) ? n0 : m0;
        const __half* g = sp + (size_t)(rb + row) * N + k0 + sub * 8;
        uint32_t d = stg + buf * BUFB + row * (STRIDE * 2) + sub * 16;
        asm volatile("cp.async.cg.shared.global [%0], [%1], 16;"
                     :: "r"(d), "l"(__cvta_generic_to_global(g)));
    }
    asm volatile("cp.async.commit_group;" ::: "memory");
}

// ---------------------------------------------------------------------------
// mode 0: C = I - S + 0.5*S*S  (S = X)     write split (and mirror)
// mode 1: C = S*S                          write split (and mirror)
// mode 2: C = S*S                          no write; ||C||_F^2 -> g_betti
// ab: 0 = src A bufs / dst B bufs ; 1 = reversed.
// ---------------------------------------------------------------------------
__global__ void __launch_bounds__(256, 1) gemmH(int mode, int ab) {
    extern __shared__ char dsm[];
    __shared__ double fred[256];

    const int tid  = threadIdx.x;
    const int lane = tid & 31;
    const int wid  = tid >> 5;
    const int wr   = wid & 1;      // 2 warp-rows of 64
    const int wc   = wid >> 1;     // 4 warp-cols of 32
    const int t    = blockIdx.z;

    // blockIdx.x in [0,21) -> upper-triangular (bm, bn), bm <= bn
    int rem = blockIdx.x, bm = 0, cnt = 6;
    while (rem >= cnt) { rem -= cnt; ++bm; --cnt; }
    const int bn = bm + rem;
    const int ctaM = bm * 128, ctaN = bn * 128;

    const __half* __restrict__ Shi = (ab ? g_Bhi : g_Ahi) + (size_t)t * NNB;
    const __half* __restrict__ Slo = (ab ? g_Blo : g_Alo) + (size_t)t * NNB;
    __half* __restrict__ Dhi       = (ab ? g_Ahi : g_Bhi) + (size_t)t * NNB;
    __half* __restrict__ Dlo       = (ab ? g_Alo : g_Blo) + (size_t)t * NNB;

    const uint32_t sbase = smem_u32(dsm);
    const uint32_t aoff = ((wr * 64 + ((lane >> 3) & 1) * 8 + (lane & 7)) * STRIDE
                           + (lane >> 4) * 8) * 2;
    const uint32_t boff = ((wc * 32 + (lane >> 4) * 8 + (lane & 7)) * STRIDE
                           + ((lane >> 3) & 1) * 8) * 2;

    float acc[4][4][4];
#pragma unroll
    for (int a = 0; a < 4; ++a)
#pragma unroll
        for (int b = 0; b < 4; ++b)
#pragma unroll
            for (int e = 0; e < 4; ++e) acc[a][b][e] = 0.0f;

    issue_stage(sbase, Shi, Slo, ctaM, ctaN, 0, tid);
    issue_stage(sbase + STAGE_B, Shi, Slo, ctaM, ctaN, KS, tid);

    for (int s = 0; s < NSTG; ++s) {
        asm volatile("cp.async.wait_group 1;" ::: "memory");
        __syncthreads();
        const uint32_t stg = sbase + (s % 3) * STAGE_B;
#pragma unroll
        for (int kk = 0; kk < 2; ++kk) {
            uint32_t ah[4][4], al[4][4], bh[2][4], bl[2][4];
#pragma unroll
            for (int mt = 0; mt < 4; ++mt) {
                uint32_t addr = stg + aoff + (uint32_t)((mt * 16 * STRIDE + kk * 16) * 2);
                LDSM4(ah[mt], addr);
                LDSM4(al[mt], addr + BUFB);
            }
#pragma unroll
            for (int p = 0; p < 2; ++p) {
                uint32_t addr = stg + 2 * BUFB + boff
                              + (uint32_t)((p * 16 * STRIDE + kk * 16) * 2);
                LDSM4(bh[p], addr);
                LDSM4(bl[p], addr + BUFB);
            }
#pragma unroll
            for (int mt = 0; mt < 4; ++mt)
#pragma unroll
                for (int nt = 0; nt < 4; ++nt) {
                    int p = nt >> 1, h = (nt & 1) * 2;
                    MMA(acc[mt][nt], ah[mt], bh[p][h], bh[p][h + 1]);
                    MMA(acc[mt][nt], ah[mt], bl[p][h], bl[p][h + 1]);
                    MMA(acc[mt][nt], al[mt], bh[p][h], bh[p][h + 1]);
                }
        }
        __syncthreads();
        if (s + 2 < NSTG)
            issue_stage(sbase + ((s + 2) % 3) * STAGE_B, Shi, Slo,
                        ctaM, ctaN, (s + 2) * KS, tid);
        else
            asm volatile("cp.async.commit_group;" ::: "memory");
    }
    __syncthreads();   // all warps done with pipeline smem

    const int g = lane >> 2, tig = lane & 3;

    if (mode == 2) {
        double fr = 0.0;
#pragma unroll
        for (int mt = 0; mt < 4; ++mt)
#pragma unroll
            for (int nt = 0; nt < 4; ++nt)
#pragma unroll
                for (int e = 0; e < 4; ++e) {
                    float v = acc[mt][nt][e] * (1.0f / 65536.0f);
                    fr += (double)v * (double)v;
                }
        if (bm != bn) fr *= 2.0;
        fred[tid] = fr;
        __syncthreads();
        for (int s2 = 128; s2 > 0; s2 >>= 1) {
            if (tid < s2) fred[tid] += fred[tid + s2];
            __syncthreads();
        }
        if (tid == 0) atomicAdd(&g_betti[t], fred[0]);
        return;
    }

    __half* Th = (__half*)dsm;          // transpose hi, 128 rows stride 136
    __half* Tl = Th + 128 * 136;
    const bool mirror = (bm != bn);

#pragma unroll
    for (int mt = 0; mt < 4; ++mt)
#pragma unroll
        for (int nt = 0; nt < 4; ++nt) {
            int rl = wr * 64 + mt * 16 + g;
            int cl = wc * 32 + nt * 8 + 2 * tig;
#pragma unroll
            for (int h2 = 0; h2 < 2; ++h2) {
                int rr = rl + h2 * 8;
                int r  = ctaM + rr;
                int c  = ctaN + cl;
                float v0 = acc[mt][nt][2 * h2 + 0];
                float v1 = acc[mt][nt][2 * h2 + 1];
                if (mode == 0) {
                    __half2 xh = *(const __half2*)(Shi + (size_t)r * N + c);
                    __half2 xl = *(const __half2*)(Slo + (size_t)r * N + c);
                    v0 = v0 * (0.5f / 256.0f) - (__low2float(xh) + __low2float(xl))
                       + ((r == c) ? 256.0f : 0.0f);
                    v1 = v1 * (0.5f / 256.0f) - (__high2float(xh) + __high2float(xl))
                       + ((r == c + 1) ? 256.0f : 0.0f);
                } else {
                    v0 *= (1.0f / 256.0f);
                    v1 *= (1.0f / 256.0f);
                }
                __half h0 = __float2half_rn(v0);
                __half l0 = __float2half_rn(v0 - __half2float(h0));
                __half h1 = __float2half_rn(v1);
                __half l1 = __float2half_rn(v1 - __half2float(h1));
                *(__half2*)(Dhi + (size_t)r * N + c) = __halves2half2(h0, h1);
                *(__half2*)(Dlo + (size_t)r * N + c) = __halves2half2(l0, l1);
                if (mirror) {
                    Th[(cl) * 136 + rr]     = h0;
                    Th[(cl + 1) * 136 + rr] = h1;
                    Tl[(cl) * 136 + rr]     = l0;
                    Tl[(cl + 1) * 136 + rr] = l1;
                }
            }
        }

    if (mirror) {
        __syncthreads();
#pragma unroll
        for (int i = 0; i < 8; ++i) {
            int ch  = tid + i * 256;       // 2048 16B chunks
            int row = ch >> 4, sub = ch & 15;
            float4 vh = *(const float4*)(Th + row * 136 + sub * 8);
            float4 vl = *(const float4*)(Tl + row * 136 + sub * 8);
            *(float4*)(Dhi + (size_t)(ctaN + row) * N + ctaM + sub * 8) = vh;
            *(float4*)(Dlo + (size_t)(ctaN + row) * N + ctaM + sub * 8) = vl;
        }
    }
}

// -------------------- Betti curve -> landscapes ----------------------------
__global__ void finalKernel(float* __restrict__ out) {
    int tid = threadIdx.x;  // 128 threads
    __shared__ float sb[NT];
    __shared__ float sbi[RES];
    __shared__ float ssm[RES];
    __shared__ float red[128];

    if (tid < NT) sb[tid] = (float)g_betti[tid];
    __syncthreads();

    if (tid < RES) {
        float pos  = (float)tid * (49.0f / 99.0f);
        int   i0   = (int)floorf(pos);
        if (i0 > 48) i0 = 48;
        if (i0 < 0)  i0 = 0;
        float frac = pos - (float)i0;
        sbi[tid] = sb[i0] * (1.0f - frac) + sb[i0 + 1] * frac;
    }
    __syncthreads();

    red[tid] = (tid < RES) ? sbi[tid] : -1e30f;
    __syncthreads();
    for (int s = 64; s > 0; s >>= 1) {
        if (tid < s) red[tid] = fmaxf(red[tid], red[tid + s]);
        __syncthreads();
    }
    float bmax = red[0];
    __syncthreads();
    if (tid < RES) out[tid] = sbi[tid] / (bmax + 1e-8f);

    for (int k = 1; k < NL; ++k) {
        int ks = 2 * k + 1, pad = k;
        __syncthreads();
        if (tid < RES) {
            float s = 0.0f;
            for (int j = -pad; j <= pad; ++j) {
                int idx = tid + j;
                idx = idx < 0 ? 0 : (idx > RES - 1 ? RES - 1 : idx);
                s += sbi[idx];
            }
            ssm[tid] = s / (float)ks;
        }
        __syncthreads();
        float d = 0.0f;
        if (tid < RES)
            d = (tid < RES - 1) ? (ssm[tid + 1] - ssm[tid])
                                : (ssm[RES - 1] - ssm[RES - 2]);
        red[tid] = (tid < RES) ? fabsf(d) : 0.0f;
        __syncthreads();
        for (int s2 = 64; s2 > 0; s2 >>= 1) {
            if (tid < s2) red[tid] = fmaxf(red[tid], red[tid + s2]);
            __syncthreads();
        }
        float dmax = red[0];
        __syncthreads();
        if (tid < RES) out[k * RES + tid] = d / (dmax + 1e-8f);
    }
}

// ---------------------------------------------------------------------------
extern "C" void kernel_launch(void* const* d_in, const int* in_sizes, int n_in,
                              void* d_out, int out_size) {
    const float* pts = (const float*)d_in[0];
    float* out = (float*)d_out;
    (void)in_sizes; (void)n_in; (void)out_size;

    static bool attr_set = false;
    if (!attr_set) {
        cudaFuncSetAttribute(gemmH, cudaFuncAttributeMaxDynamicSharedMemorySize,
                             SMEM_BYTES);
        attr_set = true;
    }

    initKernel<<<1, 64>>>();
    distKernel<<<dim3(N, 3), 256>>>(pts);
    buildXKernel<<<dim3(N, NT), 256>>>();

    dim3 gg(21, 1, NT);  // upper-tri 128x128 blocks x thresholds
    gemmH<<<gg, 256, SMEM_BYTES>>>(0, 0);          // X(A) -> B0 = I-X+X^2/2 (B)
    for (int s = 1; s <= 11; ++s)                  // 11 squarings, ping-pong
        gemmH<<<gg, 256, SMEM_BYTES>>>(1, s & 1);  // odd: B->A, even: A->B
    gemmH<<<gg, 256, SMEM_BYTES>>>(2, 0);          // 12th squaring + frobenius
    finalKernel<<<1, 128>>>(out);
}